// round 1
// baseline (speedup 1.0000x reference)
#include <cuda_runtime.h>
#include <cstdint>

// Problem constants
#define BATCH 8
#define INC 128
#define OUTC 256
#define HH 64
#define WW 64
#define NPT 9
#define Q_TOT 36864        // h*w*N = 64*64*9 per batch
#define P_TOT 294912       // BATCH * Q_TOT
#define PTILES 2304        // P_TOT / 128

typedef unsigned long long u64;

// -------- scratch (static device globals; no allocation at runtime) --------
__device__ float  dX[37748736];        // [c][p]  128 * 294912, 151MB
__device__ int4   dIdx[P_TOT];         // 4 gather indices per p
__device__ float4 dWt[P_TOT];          // 4 bilinear weights per p
__device__ float  dCwT[INC * OUTC];    // transposed 1x1 weights [c][o]
__device__ float  dPsum[OUTC * PTILES];// o-major partial sums
__device__ float  dPsq[OUTC * PTILES];
__device__ float  dScale[OUTC];
__device__ float  dShift[OUTC];

// -------- f32x2 packed-FMA helpers (Blackwell FFMA2: 2x fp32 throughput) ----
__device__ __forceinline__ void ffma2(u64 &d, u64 a, u64 b) {
    asm("fma.rn.f32x2 %0, %1, %2, %0;" : "+l"(d) : "l"(a), "l"(b));
}
__device__ __forceinline__ u64 dup2(float v) {
    u64 r; asm("mov.b64 %0, {%1, %1};" : "=l"(r) : "f"(v)); return r;
}
__device__ __forceinline__ void unpack2(u64 v, float &lo, float &hi) {
    asm("mov.b64 {%0, %1}, %2;" : "=f"(lo), "=f"(hi) : "l"(v));
}

// ---------------------------------------------------------------------------
// Kernel 0: transpose cw (256,128) -> cwT (128,256)
// ---------------------------------------------------------------------------
__global__ void kTrans(const float* __restrict__ cw) {
    int i = blockIdx.x * 256 + threadIdx.x;      // i = c*256 + o
    if (i < INC * OUTC) {
        int c = i >> 8;
        int o = i & 255;
        dCwT[i] = cw[o * INC + c];
    }
}

// ---------------------------------------------------------------------------
// Kernel 1: offset conv (3x3, 128->18) + compute bilinear gather idx/weights
// grid (16 hgroups, 8 b), block 256 = 4 h-rows x 64 w
// ---------------------------------------------------------------------------
__global__ void __launch_bounds__(256) kOffsets(
    const float* __restrict__ x,
    const float* __restrict__ pw,
    const float* __restrict__ pb)
{
    __shared__ float pws[10368];   // [cl*9+tap][18], 41.5KB, half of channels

    int b  = blockIdx.y;
    int hg = blockIdx.x;
    int tid = threadIdx.x;
    int hh = tid >> 6;
    int w  = tid & 63;
    int h  = hg * 4 + hh;

    u64 acc[9];
    #pragma unroll
    for (int i = 0; i < 9; i++) acc[i] = 0ull;

    for (int half = 0; half < 2; half++) {
        __syncthreads();
        // load pw for channels [half*64, half*64+64): coalesced global reads
        for (int s = tid; s < 10368; s += 256) {
            int o = s / 576;           // 0..17
            int ct = s - o * 576;      // c_local*9 + tap
            pws[ct * 18 + o] = pw[o * 1152 + half * 576 + ct];
        }
        __syncthreads();

        for (int cl = 0; cl < 64; cl++) {
            const float* img = x + ((b * INC + half * 64 + cl) << 12);
            #pragma unroll
            for (int kh = 0; kh < 3; kh++) {
                int xr = h + kh - 1;
                bool rvalid = ((unsigned)xr < 64u);
                #pragma unroll
                for (int kw = 0; kw < 3; kw++) {
                    int xc = w + kw - 1;
                    float v = (rvalid && (unsigned)xc < 64u)
                              ? __ldg(img + xr * 64 + xc) : 0.f;
                    u64 v2 = dup2(v);
                    const float* wr = &pws[(cl * 9 + kh * 3 + kw) * 18];
                    #pragma unroll
                    for (int o2 = 0; o2 < 9; o2++)
                        ffma2(acc[o2], v2, *(const u64*)(wr + 2 * o2));
                }
            }
        }
    }

    float off[18];
    #pragma unroll
    for (int i = 0; i < 9; i++) unpack2(acc[i], off[2 * i], off[2 * i + 1]);

    const float step = 6.2831855f / 9.0f;
    int pbase = (b * 4096 + h * 64 + w) * NPT;

    #pragma unroll
    for (int n = 0; n < NPT; n++) {
        float ang = step * (float)n;
        float px = off[n]     + __ldg(pb + n)     + cosf(ang) + (float)h;
        float py = off[9 + n] + __ldg(pb + 9 + n) + sinf(ang) + (float)w;
        float fx = floorf(px), fy = floorf(py);
        float qltx = fminf(fmaxf(fx,       0.f), 63.f);
        float qlty = fminf(fmaxf(fy,       0.f), 63.f);
        float qrbx = fminf(fmaxf(fx + 1.f, 0.f), 63.f);
        float qrby = fminf(fmaxf(fy + 1.f, 0.f), 63.f);
        float pxc  = fminf(fmaxf(px, 0.f), 63.f);
        float pyc  = fminf(fmaxf(py, 0.f), 63.f);
        float dltx = 1.f + (qltx - pxc), dlty = 1.f + (qlty - pyc);
        float drbx = 1.f - (qrbx - pxc), drby = 1.f - (qrby - pyc);
        int iltx = (int)qltx, ilty = (int)qlty;
        int irbx = (int)qrbx, irby = (int)qrby;
        dIdx[pbase + n] = make_int4(iltx * 64 + ilty, irbx * 64 + irby,
                                    iltx * 64 + irby, irbx * 64 + ilty);
        dWt[pbase + n]  = make_float4(dltx * dlty, drbx * drby,
                                      dltx * drby, drbx * dlty);
    }
}

// ---------------------------------------------------------------------------
// Kernel 2: bilinear gather -> X[c][p]  (x images live in L2: 16.8MB)
// grid (32 hw-chunks, 8 b, 4 c-groups), block 256
// ---------------------------------------------------------------------------
__global__ void __launch_bounds__(256) kGather(const float* __restrict__ x) {
    __shared__ int4   sI[1152];
    __shared__ float4 sW[1152];

    int chunk = blockIdx.x;   // 128 hw positions -> 1152 p
    int b     = blockIdx.y;
    int cg    = blockIdx.z;
    int tid   = threadIdx.x;
    int pbase = b * Q_TOT + chunk * 1152;

    for (int t = tid; t < 1152; t += 256) {
        sI[t] = dIdx[pbase + t];
        sW[t] = dWt[pbase + t];
    }
    __syncthreads();

    for (int cl = 0; cl < 32; cl++) {
        int c = cg * 32 + cl;
        const float* img = x + ((b * INC + c) << 12);
        float* dst = dX + (size_t)c * P_TOT + pbase;
        for (int t = tid; t < 1152; t += 256) {
            int4 id = sI[t];
            float4 wv = sW[t];
            float v = wv.x * __ldg(img + id.x);
            v = fmaf(wv.y, __ldg(img + id.y), v);
            v = fmaf(wv.z, __ldg(img + id.z), v);
            v = fmaf(wv.w, __ldg(img + id.w), v);
            dst[t] = v;
        }
    }
}

// ---------------------------------------------------------------------------
// Kernel 3: GEMM y = cwT^T * X, 128(o) x 128(p) tiles, K=128, FFMA2 packed.
// Writes y into d_out and deterministic per-(o, ptile) BN partials.
// grid (2304 ptiles, 2 otiles), block 256 (16 to x 16 tp), 8 o x 8 p / thread
// ---------------------------------------------------------------------------
__global__ void __launch_bounds__(256) kGemm(float* __restrict__ out) {
    __shared__ float As[16][128];    // [k][o]
    __shared__ float Bsd[16][256];   // [k][2p] duplicated values for FFMA2
    __shared__ float red[16][128];

    int ptile = blockIdx.x;
    int otile = blockIdx.y;
    int pbase = ptile * 128;
    int o0    = otile * 128;
    int tid = threadIdx.x;
    int to = tid >> 4;   // 0..15 -> 8 o's
    int tp = tid & 15;   // 0..15 -> p = tp + 16*j (conflict-free smem)

    u64 acc[4][8];
    #pragma unroll
    for (int i = 0; i < 4; i++)
        #pragma unroll
        for (int j = 0; j < 8; j++) acc[i][j] = 0ull;

    #pragma unroll 1
    for (int kc = 0; kc < 8; kc++) {
        __syncthreads();
        #pragma unroll
        for (int r = 0; r < 8; r++) {
            int idx = tid + r * 256;
            int k = idx >> 7;
            int col = idx & 127;
            As[k][col] = __ldg(&dCwT[(kc * 16 + k) * 256 + o0 + col]);
            float v = dX[(size_t)(kc * 16 + k) * P_TOT + pbase + col];
            *(float2*)&Bsd[k][2 * col] = make_float2(v, v);
        }
        __syncthreads();
        #pragma unroll
        for (int k = 0; k < 16; k++) {
            u64 a[4], bb[8];
            const float* ar = &As[k][to * 8];
            #pragma unroll
            for (int i = 0; i < 4; i++) a[i] = *(const u64*)(ar + 2 * i);
            const float* br = &Bsd[k][2 * tp];
            #pragma unroll
            for (int j = 0; j < 8; j++) bb[j] = *(const u64*)(br + 32 * j);
            #pragma unroll
            for (int i = 0; i < 4; i++)
                #pragma unroll
                for (int j = 0; j < 8; j++) ffma2(acc[i][j], a[i], bb[j]);
        }
    }

    // epilogue: write y + per-o partial sum / sumsq over this p-tile
    int b  = pbase / Q_TOT;
    int q0 = pbase - b * Q_TOT;
    float sums[8], sqs[8];
    #pragma unroll
    for (int i = 0; i < 4; i++) {
        float slo = 0.f, shi = 0.f, qlo = 0.f, qhi = 0.f;
        int olo = o0 + to * 8 + 2 * i;
        float* rlo = out + (size_t)(b * OUTC + olo) * Q_TOT + q0 + tp;
        float* rhi = rlo + Q_TOT;
        #pragma unroll
        for (int j = 0; j < 8; j++) {
            float lo, hi;
            unpack2(acc[i][j], lo, hi);
            rlo[16 * j] = lo;
            rhi[16 * j] = hi;
            slo += lo; qlo += lo * lo;
            shi += hi; qhi += hi * hi;
        }
        sums[2 * i] = slo; sums[2 * i + 1] = shi;
        sqs[2 * i]  = qlo; sqs[2 * i + 1]  = qhi;
    }

    #pragma unroll
    for (int i = 0; i < 8; i++) red[tp][to * 8 + i] = sums[i];
    __syncthreads();
    if (tid < 128) {
        float t = 0.f;
        #pragma unroll
        for (int r = 0; r < 16; r++) t += red[r][tid];
        dPsum[(size_t)(o0 + tid) * PTILES + ptile] = t;
    }
    __syncthreads();
    #pragma unroll
    for (int i = 0; i < 8; i++) red[tp][to * 8 + i] = sqs[i];
    __syncthreads();
    if (tid < 128) {
        float t = 0.f;
        #pragma unroll
        for (int r = 0; r < 16; r++) t += red[r][tid];
        dPsq[(size_t)(o0 + tid) * PTILES + ptile] = t;
    }
}

// ---------------------------------------------------------------------------
// Kernel 4: reduce partials -> scale/shift per channel (deterministic tree)
// grid 256 (one block per o), block 256
// ---------------------------------------------------------------------------
__global__ void kStats(const float* __restrict__ gamma,
                       const float* __restrict__ beta) {
    __shared__ float rs[256], rq[256];
    int o = blockIdx.x;
    int t = threadIdx.x;
    float s = 0.f, sq = 0.f;
    #pragma unroll
    for (int r = 0; r < 9; r++) {          // 2304 = 9 * 256
        int pt = t + 256 * r;
        s  += dPsum[(size_t)o * PTILES + pt];
        sq += dPsq[(size_t)o * PTILES + pt];
    }
    rs[t] = s; rq[t] = sq;
    __syncthreads();
    for (int st = 128; st > 0; st >>= 1) {
        if (t < st) { rs[t] += rs[t + st]; rq[t] += rq[t + st]; }
        __syncthreads();
    }
    if (t == 0) {
        float mean = rs[0] / (float)P_TOT;
        float var  = rq[0] / (float)P_TOT - mean * mean;
        float sc = __ldg(gamma + o) * rsqrtf(var + 1e-5f);
        dScale[o] = sc;
        dShift[o] = __ldg(beta + o) - mean * sc;
    }
}

// ---------------------------------------------------------------------------
// Kernel 5: in-place normalize + SiLU over d_out (float4)
// 73728 blocks x 256 threads = 18,874,368 float4 (exact)
// ---------------------------------------------------------------------------
__global__ void __launch_bounds__(256) kSilu(float* __restrict__ out) {
    int i = blockIdx.x * 256 + threadIdx.x;      // float4 index
    float4 v = ((float4*)out)[i];
    int o = (i / 9216) & 255;                    // 9216 float4 per (b,o) row
    float sc = dScale[o], sh = dShift[o];
    float yn;
    yn = fmaf(v.x, sc, sh); v.x = yn / (1.f + expf(-yn));
    yn = fmaf(v.y, sc, sh); v.y = yn / (1.f + expf(-yn));
    yn = fmaf(v.z, sc, sh); v.z = yn / (1.f + expf(-yn));
    yn = fmaf(v.w, sc, sh); v.w = yn / (1.f + expf(-yn));
    ((float4*)out)[i] = v;
}

// ---------------------------------------------------------------------------
extern "C" void kernel_launch(void* const* d_in, const int* in_sizes, int n_in,
                              void* d_out, int out_size) {
    const float* x     = (const float*)d_in[0];
    const float* pw    = (const float*)d_in[1];
    const float* pb    = (const float*)d_in[2];
    const float* cw    = (const float*)d_in[3];
    const float* gamma = (const float*)d_in[4];
    const float* beta  = (const float*)d_in[5];
    float* out = (float*)d_out;

    kTrans  <<<128, 256>>>(cw);
    kOffsets<<<dim3(16, 8), 256>>>(x, pw, pb);
    kGather <<<dim3(32, 8, 4), 256>>>(x);
    kGemm   <<<dim3(PTILES, 2), 256>>>(out);
    kStats  <<<256, 256>>>(gamma, beta);
    kSilu   <<<73728, 256>>>(out);
}

// round 6
// speedup vs baseline: 2.1048x; 2.1048x over previous
#include <cuda_runtime.h>
#include <cstdint>

// Problem constants
#define BATCH 8
#define INC 128
#define OUTC 256
#define NPT 9
#define Q_TOT 36864        // h*w*N per batch
#define P_TOT 294912       // BATCH * Q_TOT
#define PTILES 2304        // P_TOT / 128
#define TPB 288            // ptiles per batch

typedef unsigned long long u64;

// -------- scratch (static device globals; no runtime allocation) -----------
__device__ float  dX[(size_t)P_TOT * INC];   // [p][c] p-major, tf32-rounded
__device__ float  dCwA[OUTC * INC];          // [o][c] tf32-rounded weights
__device__ float  dXT[BATCH * 4096 * INC];   // x transposed [b][hw][c]
__device__ int4   dIdx[P_TOT];
__device__ float4 dWt[P_TOT];
__device__ float  dPsum[OUTC * PTILES];
__device__ float  dPsq[OUTC * PTILES];
__device__ float  dScale[OUTC];
__device__ float  dShift[OUTC];

// -------- helpers ----------------------------------------------------------
__device__ __forceinline__ void ffma2(u64 &d, u64 a, u64 b) {
    asm("fma.rn.f32x2 %0, %1, %2, %0;" : "+l"(d) : "l"(a), "l"(b));
}
__device__ __forceinline__ u64 dup2(float v) {
    u64 r; asm("mov.b64 %0, {%1, %1};" : "=l"(r) : "f"(v)); return r;
}
__device__ __forceinline__ void unpack2(u64 v, float &lo, float &hi) {
    asm("mov.b64 {%0, %1}, %2;" : "=f"(lo), "=f"(hi) : "l"(v));
}
__device__ __forceinline__ float tf32r(float v) {
    float r; asm("cvt.rna.tf32.f32 %0, %1;" : "=f"(r) : "f"(v)); return r;
}
__device__ __forceinline__ uint32_t smem_u32(const void* p) {
    uint32_t a; asm("{ .reg .u64 t; cvta.to.shared.u64 t, %1; cvt.u32.u64 %0, t; }"
                    : "=r"(a) : "l"(p));
    return a;
}
__device__ __forceinline__ void cp16(void* dst_smem, const void* src) {
    uint32_t d = smem_u32(dst_smem);
    asm volatile("cp.async.cg.shared.global [%0], [%1], 16;"
                 :: "r"(d), "l"(src) : "memory");
}
#define CP_COMMIT() asm volatile("cp.async.commit_group;" ::: "memory")
#define CP_WAIT(N)  asm volatile("cp.async.wait_group %0;" :: "n"(N) : "memory")

// m16n8k8 tf32 HMMA (sm_80+, no 'a' feature needed)
__device__ __forceinline__ void mma8(float* c, const uint32_t* a, const uint32_t* b) {
    asm volatile("mma.sync.aligned.m16n8k8.row.col.f32.tf32.tf32.f32 "
                 "{%0,%1,%2,%3}, {%4,%5,%6,%7}, {%8,%9}, {%0,%1,%2,%3};"
                 : "+f"(c[0]), "+f"(c[1]), "+f"(c[2]), "+f"(c[3])
                 : "r"(a[0]), "r"(a[1]), "r"(a[2]), "r"(a[3]),
                   "r"(b[0]), "r"(b[1]));
}

// ---------------------------------------------------------------------------
// Kernel 0: weights tf32-round (A stays [o][c] row-major)
// ---------------------------------------------------------------------------
__global__ void kTrans(const float* __restrict__ cw) {
    int i = blockIdx.x * 256 + threadIdx.x;
    dCwA[i] = tf32r(cw[i]);
}

// ---------------------------------------------------------------------------
// Kernel 0b: transpose x [b][c][hw] -> xT [b][hw][c]
// ---------------------------------------------------------------------------
__global__ void __launch_bounds__(256) kXpose(const float* __restrict__ x) {
    __shared__ float s[128][33];
    int b = blockIdx.y, hw0 = blockIdx.x * 32, tid = threadIdx.x;
    #pragma unroll
    for (int k2 = 0; k2 < 16; k2++) {
        int idx = tid + k2 * 256;
        int c = idx >> 5, j = idx & 31;
        s[c][j] = __ldg(x + (((size_t)(b * 128 + c)) << 12) + hw0 + j);
    }
    __syncthreads();
    int r = tid >> 3, c4 = (tid & 7) * 4;
    #pragma unroll
    for (int k2 = 0; k2 < 4; k2++) {
        int c = k2 * 32 + c4;
        float4 v = make_float4(s[c][r], s[c + 1][r], s[c + 2][r], s[c + 3][r]);
        *(float4*)(dXT + ((size_t)(b * 4096 + hw0 + r)) * 128 + c) = v;
    }
}

// ---------------------------------------------------------------------------
// Kernel 1: offset conv (3x3, 128->18) + bilinear idx/weights
// ---------------------------------------------------------------------------
__global__ void __launch_bounds__(256) kOffsets(
    const float* __restrict__ x,
    const float* __restrict__ pw,
    const float* __restrict__ pb)
{
    __shared__ float pws[10368];

    int b  = blockIdx.y;
    int hg = blockIdx.x;
    int tid = threadIdx.x;
    int hh = tid >> 6;
    int w  = tid & 63;
    int h  = hg * 4 + hh;

    u64 acc[9];
    #pragma unroll
    for (int i = 0; i < 9; i++) acc[i] = 0ull;

    for (int half = 0; half < 2; half++) {
        __syncthreads();
        for (int s = tid; s < 10368; s += 256) {
            int o = s / 576;
            int ct = s - o * 576;
            pws[ct * 18 + o] = pw[o * 1152 + half * 576 + ct];
        }
        __syncthreads();

        for (int cl = 0; cl < 64; cl++) {
            const float* img = x + ((b * INC + half * 64 + cl) << 12);
            #pragma unroll
            for (int kh = 0; kh < 3; kh++) {
                int xr = h + kh - 1;
                bool rvalid = ((unsigned)xr < 64u);
                #pragma unroll
                for (int kw = 0; kw < 3; kw++) {
                    int xc = w + kw - 1;
                    float v = (rvalid && (unsigned)xc < 64u)
                              ? __ldg(img + xr * 64 + xc) : 0.f;
                    u64 v2 = dup2(v);
                    const float* wr = &pws[(cl * 9 + kh * 3 + kw) * 18];
                    #pragma unroll
                    for (int o2 = 0; o2 < 9; o2++)
                        ffma2(acc[o2], v2, *(const u64*)(wr + 2 * o2));
                }
            }
        }
    }

    float off[18];
    #pragma unroll
    for (int i = 0; i < 9; i++) unpack2(acc[i], off[2 * i], off[2 * i + 1]);

    const float step = 6.2831855f / 9.0f;
    int pbase = (b * 4096 + h * 64 + w) * NPT;

    #pragma unroll
    for (int n = 0; n < NPT; n++) {
        float ang = step * (float)n;
        float px = off[n]     + __ldg(pb + n)     + cosf(ang) + (float)h;
        float py = off[9 + n] + __ldg(pb + 9 + n) + sinf(ang) + (float)w;
        float fx = floorf(px), fy = floorf(py);
        float qltx = fminf(fmaxf(fx,       0.f), 63.f);
        float qlty = fminf(fmaxf(fy,       0.f), 63.f);
        float qrbx = fminf(fmaxf(fx + 1.f, 0.f), 63.f);
        float qrby = fminf(fmaxf(fy + 1.f, 0.f), 63.f);
        float pxc  = fminf(fmaxf(px, 0.f), 63.f);
        float pyc  = fminf(fmaxf(py, 0.f), 63.f);
        float dltx = 1.f + (qltx - pxc), dlty = 1.f + (qlty - pyc);
        float drbx = 1.f - (qrbx - pxc), drby = 1.f - (qrby - pyc);
        int iltx = (int)qltx, ilty = (int)qlty;
        int irbx = (int)qrbx, irby = (int)qrby;
        dIdx[pbase + n] = make_int4(iltx * 64 + ilty, irbx * 64 + irby,
                                    iltx * 64 + irby, irbx * 64 + ilty);
        dWt[pbase + n]  = make_float4(dltx * dlty, drbx * drby,
                                      dltx * drby, drbx * dlty);
    }
}

// ---------------------------------------------------------------------------
// Kernel 2: bilinear gather from channel-last xT -> dX [p][c], coalesced.
// grid 2304 (one block per ptile), block 256 (8 warps). Warp-per-point,
// lanes cover 128 channels via float4 -> 4 coalesced LDG.128 + 1 STG.128.
// ---------------------------------------------------------------------------
__global__ void __launch_bounds__(256) kGather() {
    __shared__ int4   sI[128];
    __shared__ float4 sW[128];

    int ptile = blockIdx.x;
    int tid = threadIdx.x, wid = tid >> 5, lid = tid & 31;
    int b = ptile / TPB;
    int p0 = ptile * 128;

    if (tid < 128) { sI[tid] = dIdx[p0 + tid]; sW[tid] = dWt[p0 + tid]; }
    __syncthreads();

    const float4* xb = (const float4*)(dXT + ((size_t)b << 19));

    #pragma unroll 4
    for (int k = 0; k < 16; k++) {
        int p = wid * 16 + k;
        int4 id = sI[p];
        float4 wv = sW[p];
        float4 A  = __ldg(xb + (size_t)id.x * 32 + lid);
        float4 Bv = __ldg(xb + (size_t)id.y * 32 + lid);
        float4 C  = __ldg(xb + (size_t)id.z * 32 + lid);
        float4 Dv = __ldg(xb + (size_t)id.w * 32 + lid);
        float4 v;
        v.x = tf32r(fmaf(wv.w, Dv.x, fmaf(wv.z, C.x, fmaf(wv.y, Bv.x, wv.x * A.x))));
        v.y = tf32r(fmaf(wv.w, Dv.y, fmaf(wv.z, C.y, fmaf(wv.y, Bv.y, wv.x * A.y))));
        v.z = tf32r(fmaf(wv.w, Dv.z, fmaf(wv.z, C.z, fmaf(wv.y, Bv.z, wv.x * A.z))));
        v.w = tf32r(fmaf(wv.w, Dv.w, fmaf(wv.z, C.w, fmaf(wv.y, Bv.w, wv.x * A.w))));
        *(float4*)(dX + ((size_t)(p0 + p)) * 128 + 4 * lid) = v;
    }
}

// ---------------------------------------------------------------------------
// Kernel 3: mma.sync tf32 GEMM. 128(o) x 128(p) tile per CTA, K=128.
// 256 threads = 8 warps in 2(m) x 4(n); warp tile 64x32; m16n8k8 HMMA.
// A full-K in smem (stride 132: conflict-free frag loads), B chunked 16-K
// double-buffered via cp.async (stride 20: conflict-free). Epilogue writes
// y (float2, full 32B sectors) + deterministic BN partials via padded smem.
// ---------------------------------------------------------------------------
#define BST 20
#define SZ_A (128 * 132)
#define SZ_B (128 * BST)
#define SMEM_GEMM ((SZ_A + 2 * SZ_B + 128 * 17) * 4)

__global__ void __launch_bounds__(256, 2) kGemm(float* __restrict__ out) {
    extern __shared__ float sm[];
    float* As  = sm;                       // [o][132]
    float* Bs  = sm + SZ_A;                // [2][p][BST]
    float* red = sm + SZ_A + 2 * SZ_B;     // [128][17]

    const int tid = threadIdx.x, lid = tid & 31, wid = tid >> 5;
    const int wm = wid >> 2, wn = wid & 3;
    const int g = lid >> 2, t = lid & 3;
    const int otile = blockIdx.x;
    const int ptile = blockIdx.y;
    const int pbase = ptile * 128;

    // group 0: full A + B chunk 0
    const float* Ag = dCwA + otile * 16384;
    #pragma unroll
    for (int i = 0; i < 16; i++) {
        int idx = tid + i * 256;           // 4096 x 16B
        int o = idx >> 5, c = (idx & 31) * 4;
        cp16(&As[o * 132 + c], Ag + o * 128 + c);
    }
    #pragma unroll
    for (int i = 0; i < 2; i++) {
        int idx = tid + i * 256;           // 512 x 16B
        int p = idx >> 2, c = (idx & 3) * 4;
        cp16(&Bs[p * BST + c], dX + (size_t)(pbase + p) * 128 + c);
    }
    CP_COMMIT();

    float acc[4][4][4];
    #pragma unroll
    for (int mt = 0; mt < 4; mt++)
        #pragma unroll
        for (int nt = 0; nt < 4; nt++)
            #pragma unroll
            for (int r = 0; r < 4; r++) acc[mt][nt][r] = 0.f;

    #pragma unroll 1
    for (int kc = 0; kc < 8; kc++) {
        int cur = kc & 1;
        if (kc < 7) {
            int nxt = cur ^ 1;
            #pragma unroll
            for (int i = 0; i < 2; i++) {
                int idx = tid + i * 256;
                int p = idx >> 2, c = (idx & 3) * 4;
                cp16(&Bs[nxt * SZ_B + p * BST + c],
                     dX + (size_t)(pbase + p) * 128 + (kc + 1) * 16 + c);
            }
            CP_COMMIT();
            CP_WAIT(1);
        } else {
            CP_WAIT(0);
        }
        __syncthreads();

        const float* Bb = Bs + cur * SZ_B;
        #pragma unroll
        for (int k8 = 0; k8 < 2; k8++) {
            int kg = kc * 16 + k8 * 8;
            uint32_t a[4][4], b[4][2];
            #pragma unroll
            for (int mt = 0; mt < 4; mt++) {
                const float* ap = As + (wm * 64 + mt * 16 + g) * 132 + kg + t;
                a[mt][0] = __float_as_uint(ap[0]);
                a[mt][1] = __float_as_uint(ap[8 * 132]);
                a[mt][2] = __float_as_uint(ap[4]);
                a[mt][3] = __float_as_uint(ap[8 * 132 + 4]);
            }
            #pragma unroll
            for (int nt = 0; nt < 4; nt++) {
                const float* bp = Bb + (wn * 32 + nt * 8 + g) * BST + k8 * 8 + t;
                b[nt][0] = __float_as_uint(bp[0]);
                b[nt][1] = __float_as_uint(bp[4]);
            }
            #pragma unroll
            for (int mt = 0; mt < 4; mt++)
                #pragma unroll
                for (int nt = 0; nt < 4; nt++)
                    mma8(acc[mt][nt], a[mt], b[nt]);
        }
        __syncthreads();
    }

    // ---- epilogue: y stores + BN partials ----
    int bb = ptile / TPB;
    int q0 = (ptile - bb * TPB) * 128;
    float* obase = out + ((size_t)(bb * OUTC + otile * 128)) * Q_TOT + q0;

    float sv[4][2], qv[4][2];
    #pragma unroll
    for (int mt = 0; mt < 4; mt++) {
        #pragma unroll
        for (int h = 0; h < 2; h++) {
            int row = wm * 64 + mt * 16 + g + h * 8;
            float s = 0.f, sq = 0.f;
            #pragma unroll
            for (int nt = 0; nt < 4; nt++) {
                float c0 = acc[mt][nt][h * 2], c1 = acc[mt][nt][h * 2 + 1];
                int p = wn * 32 + nt * 8 + 2 * t;
                *(float2*)(obase + (size_t)row * Q_TOT + p) = make_float2(c0, c1);
                s += c0 + c1;
                sq += c0 * c0 + c1 * c1;
            }
            sv[mt][h] = s; qv[mt][h] = sq;
        }
    }

    // deterministic per-row reduction: 16 slots per row (4 warpN x 4 t)
    #pragma unroll
    for (int mt = 0; mt < 4; mt++)
        #pragma unroll
        for (int h = 0; h < 2; h++)
            red[(wm * 64 + mt * 16 + g + h * 8) * 17 + wn * 4 + t] = sv[mt][h];
    __syncthreads();
    if (tid < 128) {
        float s = 0.f;
        #pragma unroll
        for (int i = 0; i < 16; i++) s += red[tid * 17 + i];
        dPsum[(size_t)(otile * 128 + tid) * PTILES + ptile] = s;
    }
    __syncthreads();
    #pragma unroll
    for (int mt = 0; mt < 4; mt++)
        #pragma unroll
        for (int h = 0; h < 2; h++)
            red[(wm * 64 + mt * 16 + g + h * 8) * 17 + wn * 4 + t] = qv[mt][h];
    __syncthreads();
    if (tid < 128) {
        float s = 0.f;
        #pragma unroll
        for (int i = 0; i < 16; i++) s += red[tid * 17 + i];
        dPsq[(size_t)(otile * 128 + tid) * PTILES + ptile] = s;
    }
}

// ---------------------------------------------------------------------------
// Kernel 4: reduce partials -> scale/shift per channel
// ---------------------------------------------------------------------------
__global__ void kStats(const float* __restrict__ gamma,
                       const float* __restrict__ beta) {
    __shared__ float rs[256], rq[256];
    int o = blockIdx.x;
    int t = threadIdx.x;
    float s = 0.f, sq = 0.f;
    #pragma unroll
    for (int r = 0; r < 9; r++) {
        size_t base = (size_t)o * PTILES + t + 256 * r;
        s  += dPsum[base];
        sq += dPsq[base];
    }
    rs[t] = s; rq[t] = sq;
    __syncthreads();
    for (int st = 128; st > 0; st >>= 1) {
        if (t < st) { rs[t] += rs[t + st]; rq[t] += rq[t + st]; }
        __syncthreads();
    }
    if (t == 0) {
        float mean = rs[0] / (float)P_TOT;
        float var  = rq[0] / (float)P_TOT - mean * mean;
        float sc = __ldg(gamma + o) * rsqrtf(var + 1e-5f);
        dScale[o] = sc;
        dShift[o] = __ldg(beta + o) - mean * sc;
    }
}

// ---------------------------------------------------------------------------
// Kernel 5: in-place normalize + SiLU over d_out (float4)
// ---------------------------------------------------------------------------
__global__ void __launch_bounds__(256) kSilu(float* __restrict__ out) {
    int i = blockIdx.x * 256 + threadIdx.x;
    float4 v = ((float4*)out)[i];
    int o = (i / 9216) & 255;
    float sc = dScale[o], sh = dShift[o];
    float yn;
    yn = fmaf(v.x, sc, sh); v.x = yn / (1.f + expf(-yn));
    yn = fmaf(v.y, sc, sh); v.y = yn / (1.f + expf(-yn));
    yn = fmaf(v.z, sc, sh); v.z = yn / (1.f + expf(-yn));
    yn = fmaf(v.w, sc, sh); v.w = yn / (1.f + expf(-yn));
    ((float4*)out)[i] = v;
}

// ---------------------------------------------------------------------------
extern "C" void kernel_launch(void* const* d_in, const int* in_sizes, int n_in,
                              void* d_out, int out_size) {
    const float* x     = (const float*)d_in[0];
    const float* pw    = (const float*)d_in[1];
    const float* pb    = (const float*)d_in[2];
    const float* cw    = (const float*)d_in[3];
    const float* gamma = (const float*)d_in[4];
    const float* beta  = (const float*)d_in[5];
    float* out = (float*)d_out;

    cudaFuncSetAttribute(kGemm, cudaFuncAttributeMaxDynamicSharedMemorySize,
                         SMEM_GEMM);

    kTrans  <<<128, 256>>>(cw);
    kXpose  <<<dim3(128, 8), 256>>>(x);
    kOffsets<<<dim3(16, 8), 256>>>(x, pw, pb);
    kGather <<<PTILES, 256>>>();
    kGemm   <<<dim3(2, PTILES), 256, SMEM_GEMM>>>(out);
    kStats  <<<256, 256>>>(gamma, beta);
    kSilu   <<<73728, 256>>>(out);
}